// round 1
// baseline (speedup 1.0000x reference)
#include <cuda_runtime.h>
#include <cstdint>

#define LAYERS 8
#define EPS_F 1e-7f

// Folded circuit matrices: [circuit][row][col][re/im]
// M'[r][k] = (U_layers)[r][k] * phase_k, phase = {1, -i, -i, -1}
__device__ float g_M[3][4][4][2];

// ---------------------------------------------------------------------------
// Pre-kernel: 3 threads, one per circuit. Builds U = Prod_l ( P * (R0 x R1) )
// where P is the combined CNOT(0->1); CNOT(1->0) row permutation {0,2,3,1}.
// ---------------------------------------------------------------------------
__global__ void qmdn_precompute(const float* __restrict__ wp,
                                const float* __restrict__ wm,
                                const float* __restrict__ ws) {
    int q = threadIdx.x;
    if (q >= 3) return;
    const float* w = (q == 0) ? wp : (q == 1) ? wm : ws;

    float Ur[4][4], Ui[4][4];
    for (int r = 0; r < 4; r++)
        for (int c = 0; c < 4; c++) { Ur[r][c] = (r == c) ? 1.f : 0.f; Ui[r][c] = 0.f; }

    for (int l = 0; l < LAYERS; l++) {
        float R0r[2][2], R0i[2][2], R1r[2][2], R1i[2][2];
        for (int wi = 0; wi < 2; wi++) {
            float phi = w[(l * 2 + wi) * 3 + 0];
            float th  = w[(l * 2 + wi) * 3 + 1];
            float om  = w[(l * 2 + wi) * 3 + 2];
            float ct = cosf(0.5f * th), st = sinf(0.5f * th);
            float apo = 0.5f * (phi + om), amo = 0.5f * (phi - om);
            float capo = cosf(apo), sapo = sinf(apo);
            float camo = cosf(amo), samo = sinf(amo);
            float (*Rr)[2] = wi ? R1r : R0r;
            float (*Ri)[2] = wi ? R1i : R0i;
            // Rot = [[e^{-i apo} ct, -e^{+i amo} st], [e^{-i amo} st, e^{+i apo} ct]]
            Rr[0][0] =  capo * ct;  Ri[0][0] = -sapo * ct;
            Rr[0][1] = -camo * st;  Ri[0][1] = -samo * st;
            Rr[1][0] =  camo * st;  Ri[1][0] = -samo * st;
            Rr[1][1] =  capo * ct;  Ri[1][1] =  sapo * ct;
        }
        // PK = row-permuted Kronecker product
        const int src[4] = {0, 2, 3, 1};
        float Kr[4][4], Ki[4][4];
        for (int r = 0; r < 4; r++) {
            int rs = src[r], i0 = rs >> 1, j0 = rs & 1;
            for (int c = 0; c < 4; c++) {
                int i1 = c >> 1, j1 = c & 1;
                float ar = R0r[i0][i1], ai = R0i[i0][i1];
                float br = R1r[j0][j1], bi = R1i[j0][j1];
                Kr[r][c] = ar * br - ai * bi;
                Ki[r][c] = ar * bi + ai * br;
            }
        }
        // U = PK * U
        float Nr[4][4], Ni[4][4];
        for (int r = 0; r < 4; r++)
            for (int c = 0; c < 4; c++) {
                float sr = 0.f, si = 0.f;
                for (int k = 0; k < 4; k++) {
                    sr += Kr[r][k] * Ur[k][c] - Ki[r][k] * Ui[k][c];
                    si += Kr[r][k] * Ui[k][c] + Ki[r][k] * Ur[k][c];
                }
                Nr[r][c] = sr; Ni[r][c] = si;
            }
        for (int r = 0; r < 4; r++)
            for (int c = 0; c < 4; c++) { Ur[r][c] = Nr[r][c]; Ui[r][c] = Ni[r][c]; }
    }
    // Fold column phases {1, -i, -i, -1}:  -i*(a+bi) = b - a i
    for (int r = 0; r < 4; r++) {
        g_M[q][r][0][0] =  Ur[r][0]; g_M[q][r][0][1] =  Ui[r][0];
        g_M[q][r][1][0] =  Ui[r][1]; g_M[q][r][1][1] = -Ur[r][1];
        g_M[q][r][2][0] =  Ui[r][2]; g_M[q][r][2][1] = -Ur[r][2];
        g_M[q][r][3][0] = -Ur[r][3]; g_M[q][r][3][1] = -Ui[r][3];
    }
}

// ---------------------------------------------------------------------------
// Main kernel: 4 elements / thread, float4 I/O.
// out layout: [pi (B,3) | mu (B,3) | sigma (B,3)], row-major.
// ---------------------------------------------------------------------------
__global__ void __launch_bounds__(256) qmdn_main(const float4* __restrict__ x4,
                                                 float* __restrict__ out, int B) {
    __shared__ float sM[3][4][4][2];
    int tid = threadIdx.x;
    if (tid < 96) ((float*)sM)[tid] = ((const float*)g_M)[tid];
    __syncthreads();

    int t = blockIdx.x * blockDim.x + tid;    // group of 4 elements
    int nGroups = B >> 2;
    if (t >= nGroups) return;

    float4 xv = x4[t];
    float xs[4] = {xv.x, xv.y, xv.z, xv.w};

    float a[4][4];
#pragma unroll
    for (int e = 0; e < 4; e++) {
        float s0, c0, s1, c1;
        __sincosf(0.5f * xs[e], &s0, &c0);
        __sincosf(0.78539816339744831f * xs[e], &s1, &c1);
        a[e][0] = c0 * c1; a[e][1] = c0 * s1;
        a[e][2] = s0 * c1; a[e][3] = s0 * s1;
    }

    const float CLIP_LO = EPS_F;
    const float CLIP_HI = 1.0f - EPS_F;
    size_t regionStride = 3 * (size_t)B;

#pragma unroll
    for (int q = 0; q < 3; q++) {
        float o[12];
#pragma unroll
        for (int e = 0; e < 4; e++) {
            float p[4];
#pragma unroll
            for (int j = 0; j < 4; j++) {
                float re = 0.f, im = 0.f;
#pragma unroll
                for (int k = 0; k < 4; k++) {
                    re = fmaf(sM[q][j][k][0], a[e][k], re);
                    im = fmaf(sM[q][j][k][1], a[e][k], im);
                }
                p[j] = re * re + im * im;
            }
            if (q == 0) {
                // pi = p[:3] / sum(p[:3])
                float inv = __fdividef(1.0f, p[0] + p[1] + p[2]);
                o[e * 3 + 0] = p[0] * inv;
                o[e * 3 + 1] = p[1] * inv;
                o[e * 3 + 2] = p[2] * inv;
            } else {
                float pc[4];
#pragma unroll
                for (int j = 0; j < 4; j++)
                    pc[j] = fminf(fmaxf(p[j], CLIP_LO), CLIP_HI);
                if (q == 1) {
                    // mu = log(pc[:3]) - log(pc[3])
                    float l3 = __logf(pc[3]);
                    o[e * 3 + 0] = __logf(pc[0]) - l3;
                    o[e * 3 + 1] = __logf(pc[1]) - l3;
                    o[e * 3 + 2] = __logf(pc[2]) - l3;
                } else {
                    // sigma = exp(log pc[:3] - log pc[3]) == pc[:3]/pc[3]
                    float inv = __fdividef(1.0f, pc[3]);
                    o[e * 3 + 0] = pc[0] * inv;
                    o[e * 3 + 1] = pc[1] * inv;
                    o[e * 3 + 2] = pc[2] * inv;
                }
            }
        }
        // 12 consecutive floats per group -> 3 aligned float4 stores
        float4* dst = (float4*)(out + q * regionStride + (size_t)t * 12);
        dst[0] = make_float4(o[0], o[1], o[2],  o[3]);
        dst[1] = make_float4(o[4], o[5], o[6],  o[7]);
        dst[2] = make_float4(o[8], o[9], o[10], o[11]);
    }
}

extern "C" void kernel_launch(void* const* d_in, const int* in_sizes, int n_in,
                              void* d_out, int out_size) {
    const float* x  = (const float*)d_in[0];
    const float* wp = (const float*)d_in[1];
    const float* wm = (const float*)d_in[2];
    const float* ws = (const float*)d_in[3];
    float* out = (float*)d_out;
    int B = in_sizes[0];

    qmdn_precompute<<<1, 32>>>(wp, wm, ws);

    int nGroups = B >> 2;
    int threads = 256;
    int blocks = (nGroups + threads - 1) / threads;
    qmdn_main<<<blocks, threads>>>((const float4*)x, out, B);
}

// round 2
// speedup vs baseline: 1.3391x; 1.3391x over previous
#include <cuda_runtime.h>
#include <cstdint>

#define LAYERS 8
#define EPS_F 1e-7f

// ---------------------------------------------------------------------------
// Single fused kernel.
// Per-block cooperative precompute of the 3 folded circuit matrices
// (phase {1,-i,-i,-1} folded into columns), then 4 elements/thread main loop.
// out layout: [pi (B,3) | mu (B,3) | sigma (B,3)], row-major.
// ---------------------------------------------------------------------------
__global__ void __launch_bounds__(256, 4)
qmdn_fused(const float4* __restrict__ x4,
           const float* __restrict__ wp,
           const float* __restrict__ wm,
           const float* __restrict__ ws,
           float* __restrict__ out, int B) {
    __shared__ float sR[3][LAYERS][2][2][2][2];   // q, layer, wire, row, col, re/im
    __shared__ float sP[3][LAYERS][4][4][2];      // layer matrices / product workspace
    __shared__ float sM[3][4][4][2];              // final folded matrices

    int tid  = threadIdx.x;
    int wid  = tid >> 5;
    int lane = tid & 31;

    if (wid < 3) {
        int q = wid;
        const float* w = (q == 0) ? wp : (q == 1) ? wm : ws;

        // --- 1. all 16 Rot gates in parallel (lane = 2*layer + wire) ---
        if (lane < 16) {
            int l = lane >> 1, wi = lane & 1;
            float phi = w[(l * 2 + wi) * 3 + 0];
            float th  = w[(l * 2 + wi) * 3 + 1];
            float om  = w[(l * 2 + wi) * 3 + 2];
            float ct = cosf(0.5f * th), st = sinf(0.5f * th);
            float apo = 0.5f * (phi + om), amo = 0.5f * (phi - om);
            float capo = cosf(apo), sapo = sinf(apo);
            float camo = cosf(amo), samo = sinf(amo);
            sR[q][l][wi][0][0][0] =  capo * ct;  sR[q][l][wi][0][0][1] = -sapo * ct;
            sR[q][l][wi][0][1][0] = -camo * st;  sR[q][l][wi][0][1][1] = -samo * st;
            sR[q][l][wi][1][0][0] =  camo * st;  sR[q][l][wi][1][0][1] = -samo * st;
            sR[q][l][wi][1][1][0] =  capo * ct;  sR[q][l][wi][1][1][1] =  sapo * ct;
        }
        __syncwarp();

        // --- 2. per-layer PK = row-permuted Kronecker (lane = 4*r + c) ---
        if (lane < 16) {
            int r = lane >> 2, c = lane & 3;
            const int src[4] = {0, 2, 3, 1};
            int rs = src[r], i0 = rs >> 1, j0 = rs & 1, i1 = c >> 1, j1 = c & 1;
#pragma unroll
            for (int l = 0; l < LAYERS; l++) {
                float ar = sR[q][l][0][i0][i1][0], ai = sR[q][l][0][i0][i1][1];
                float br = sR[q][l][1][j0][j1][0], bi = sR[q][l][1][j0][j1][1];
                sP[q][l][r][c][0] = ar * br - ai * bi;
                sP[q][l][r][c][1] = ar * bi + ai * br;
            }
        }
        __syncwarp();

        // --- 3. log-tree product: U = PK7·PK6·...·PK0 ---
        for (int np = 4; np >= 1; np >>= 1) {
            float res[4][2];
            if (lane < 16) {
                int r = lane >> 2, c = lane & 3;
                for (int m = 0; m < np; m++) {
                    float sr = 0.f, si = 0.f;
#pragma unroll
                    for (int k = 0; k < 4; k++) {
                        float ar = sP[q][2 * m + 1][r][k][0], ai = sP[q][2 * m + 1][r][k][1];
                        float br = sP[q][2 * m][k][c][0],     bi = sP[q][2 * m][k][c][1];
                        sr += ar * br - ai * bi;
                        si += ar * bi + ai * br;
                    }
                    res[m][0] = sr; res[m][1] = si;
                }
            }
            __syncwarp();
            if (lane < 16) {
                int r = lane >> 2, c = lane & 3;
                for (int m = 0; m < np; m++) {
                    sP[q][m][r][c][0] = res[m][0];
                    sP[q][m][r][c][1] = res[m][1];
                }
            }
            __syncwarp();
        }

        // --- 4. fold column phases {1, -i, -i, -1} ---
        if (lane < 16) {
            int r = lane >> 2, c = lane & 3;
            float ur = sP[q][0][r][c][0], ui = sP[q][0][r][c][1];
            float mr, mi;
            if (c == 0)      { mr =  ur; mi =  ui; }
            else if (c == 3) { mr = -ur; mi = -ui; }
            else             { mr =  ui; mi = -ur; }   // -i*(a+bi) = b - a i
            sM[q][r][c][0] = mr;
            sM[q][r][c][1] = mi;
        }
    }
    __syncthreads();

    // ------------------- main loop: 4 elements / thread -------------------
    int t = blockIdx.x * blockDim.x + tid;
    int nGroups = B >> 2;
    if (t >= nGroups) return;

    float4 xv = x4[t];
    float xs[4] = {xv.x, xv.y, xv.z, xv.w};

    float a[4][4];
#pragma unroll
    for (int e = 0; e < 4; e++) {
        float s0, c0, s1, c1;
        __sincosf(0.5f * xs[e], &s0, &c0);
        __sincosf(0.78539816339744831f * xs[e], &s1, &c1);
        a[e][0] = c0 * c1; a[e][1] = c0 * s1;
        a[e][2] = s0 * c1; a[e][3] = s0 * s1;
    }

    const float CLIP_LO = EPS_F;
    const float CLIP_HI = 1.0f - EPS_F;
    size_t regionStride = 3 * (size_t)B;

#pragma unroll
    for (int q = 0; q < 3; q++) {
        float o[12];
#pragma unroll
        for (int e = 0; e < 4; e++) {
            float p[4];
            int nrows = (q == 0) ? 3 : 4;     // pi never uses p[3]
#pragma unroll
            for (int j = 0; j < 4; j++) {
                if (j >= nrows) break;
                float re = 0.f, im = 0.f;
#pragma unroll
                for (int k = 0; k < 4; k++) {
                    re = fmaf(sM[q][j][k][0], a[e][k], re);
                    im = fmaf(sM[q][j][k][1], a[e][k], im);
                }
                p[j] = re * re + im * im;
            }
            if (q == 0) {
                float inv = __fdividef(1.0f, p[0] + p[1] + p[2]);
                o[e * 3 + 0] = p[0] * inv;
                o[e * 3 + 1] = p[1] * inv;
                o[e * 3 + 2] = p[2] * inv;
            } else {
                float pc[4];
#pragma unroll
                for (int j = 0; j < 4; j++)
                    pc[j] = fminf(fmaxf(p[j], CLIP_LO), CLIP_HI);
                if (q == 1) {
                    float l3 = __logf(pc[3]);
                    o[e * 3 + 0] = __logf(pc[0]) - l3;
                    o[e * 3 + 1] = __logf(pc[1]) - l3;
                    o[e * 3 + 2] = __logf(pc[2]) - l3;
                } else {
                    float inv = __fdividef(1.0f, pc[3]);
                    o[e * 3 + 0] = pc[0] * inv;
                    o[e * 3 + 1] = pc[1] * inv;
                    o[e * 3 + 2] = pc[2] * inv;
                }
            }
        }
        float4* dst = (float4*)(out + q * regionStride + (size_t)t * 12);
        dst[0] = make_float4(o[0], o[1], o[2],  o[3]);
        dst[1] = make_float4(o[4], o[5], o[6],  o[7]);
        dst[2] = make_float4(o[8], o[9], o[10], o[11]);
    }
}

extern "C" void kernel_launch(void* const* d_in, const int* in_sizes, int n_in,
                              void* d_out, int out_size) {
    const float* x  = (const float*)d_in[0];
    const float* wp = (const float*)d_in[1];
    const float* wm = (const float*)d_in[2];
    const float* ws = (const float*)d_in[3];
    float* out = (float*)d_out;
    int B = in_sizes[0];

    int nGroups = B >> 2;
    int threads = 256;
    int blocks = (nGroups + threads - 1) / threads;
    qmdn_fused<<<blocks, threads>>>((const float4*)x, wp, wm, ws, out, B);
}